// round 4
// baseline (speedup 1.0000x reference)
#include <cuda_runtime.h>
#include <math.h>

#define D_MODEL 2048
#define S_LEN   2048
#define BATCH   2
#define NQ      32
#define NKV     8
#define HD      64
#define MS      (BATCH * S_LEN)   // 4096 rows

// ---------------- scratch (no allocation allowed) ----------------
__device__ float g_q[(size_t)MS * D_MODEL];      // 32 MB
__device__ float g_k[(size_t)MS * NKV * HD];     // 8 MB
__device__ float g_v[(size_t)MS * NKV * HD];     // 8 MB
__device__ float g_attn[(size_t)MS * D_MODEL];   // 32 MB

// ---------------- GEMM: C[M,N] = A[M,K] * B[N,K]^T (both row-major, K-contig) ----
#define BM 128
#define BN 128
#define BKK 16

__global__ __launch_bounds__(256) void gemm_nt(const float* __restrict__ A,
                                               const float* __restrict__ B,
                                               float* __restrict__ C,
                                               int M, int N, int K)
{
    __shared__ float As[BKK][BM + 4];
    __shared__ float Bs[BKK][BN + 4];

    const int tid = threadIdx.x;
    const int tx = tid & 15;       // 0..15 -> N microtile
    const int ty = tid >> 4;       // 0..15 -> M microtile
    const int row0 = blockIdx.y * BM;
    const int col0 = blockIdx.x * BN;

    const float* Ap = A + (size_t)row0 * K;
    const float* Bp = B + (size_t)col0 * K;

    const int lr = tid >> 2;           // 0..63
    const int lc = (tid & 3) << 2;     // 0,4,8,12

    float acc[8][8] = {};

    for (int k0 = 0; k0 < K; k0 += BKK) {
        #pragma unroll
        for (int i = 0; i < 2; i++) {
            int r = lr + i * 64;
            float4 a = *(const float4*)(Ap + (size_t)r * K + k0 + lc);
            As[lc + 0][r] = a.x; As[lc + 1][r] = a.y;
            As[lc + 2][r] = a.z; As[lc + 3][r] = a.w;
            float4 b = *(const float4*)(Bp + (size_t)r * K + k0 + lc);
            Bs[lc + 0][r] = b.x; Bs[lc + 1][r] = b.y;
            Bs[lc + 2][r] = b.z; Bs[lc + 3][r] = b.w;
        }
        __syncthreads();

        #pragma unroll
        for (int k = 0; k < BKK; k++) {
            float4 a0 = *(const float4*)&As[k][ty * 8];
            float4 a1 = *(const float4*)&As[k][ty * 8 + 4];
            float4 b0 = *(const float4*)&Bs[k][tx * 8];
            float4 b1 = *(const float4*)&Bs[k][tx * 8 + 4];
            float ar[8] = {a0.x, a0.y, a0.z, a0.w, a1.x, a1.y, a1.z, a1.w};
            float br[8] = {b0.x, b0.y, b0.z, b0.w, b1.x, b1.y, b1.z, b1.w};
            #pragma unroll
            for (int i = 0; i < 8; i++)
                #pragma unroll
                for (int j = 0; j < 8; j++)
                    acc[i][j] += ar[i] * br[j];
        }
        __syncthreads();
    }

    #pragma unroll
    for (int i = 0; i < 8; i++) {
        float* Cp = C + (size_t)(row0 + ty * 8 + i) * N + col0 + tx * 8;
        *(float4*)(Cp)     = make_float4(acc[i][0], acc[i][1], acc[i][2], acc[i][3]);
        *(float4*)(Cp + 4) = make_float4(acc[i][4], acc[i][5], acc[i][6], acc[i][7]);
    }
}

// ---------------- flash attention ----------------
// grid: (32 q-blocks, 32 q-heads, 2 batch); 256 threads.
// Each CTA: 64 query rows of one head; iterate KV in 64-row tiles.
// Thread (r = tid/4, g = tid%4): owns S-columns c = 4j+g (j=0..15) and
// O d-columns d4 = g+4u (u=0..3). Both mappings make the hot LDS.128
// streams hit 4 distinct banksets (pad=68 floats/row).
#define ATT_PAD 68
#define ATT_SMEM (3 * 64 * ATT_PAD * 4)   // 52224 B

extern __shared__ float att_smem[];

__global__ __launch_bounds__(256) void attn_kernel(const float* __restrict__ Q,
                                                   const float* __restrict__ Kg,
                                                   const float* __restrict__ Vg,
                                                   float* __restrict__ O)
{
    float* Qs = att_smem;                    // [64][68]  (pre-scaled by 1/8)
    float* Ks = att_smem + 64 * ATT_PAD;     // K tile, reused as P tile
    float* Vs = att_smem + 2 * 64 * ATT_PAD; // V tile

    const int tid = threadIdx.x;
    const int qb  = blockIdx.x;       // query block 0..31
    const int qh  = blockIdx.y;       // query head  0..31
    const int b   = blockIdx.z;
    const int kvh = qh >> 2;          // repeat_interleave: kv head = qh/4
    const int r = tid >> 2;           // 0..63 (query row in tile)
    const int g = tid & 3;            // 0..3  (column group)

    const size_t qbase = ((size_t)b * S_LEN + qb * 64) * D_MODEL + (size_t)qh * HD;
    const size_t kbase = ((size_t)b * S_LEN) * (NKV * HD) + (size_t)kvh * HD;

    // load Q tile, pre-scaled by 1/sqrt(HD)
    for (int idx = tid; idx < 64 * 16; idx += 256) {
        int rr = idx >> 4, c4 = idx & 15;
        float4 v = *(const float4*)(Q + qbase + (size_t)rr * D_MODEL + c4 * 4);
        float* dst = Qs + rr * ATT_PAD + c4 * 4;
        dst[0] = v.x * 0.125f; dst[1] = v.y * 0.125f;
        dst[2] = v.z * 0.125f; dst[3] = v.w * 0.125f;
    }

    float m = -1e30f, l = 0.f;
    float o[16] = {};   // o[u*4+w] -> d = (g+4u)*4 + w

    for (int kt = 0; kt < S_LEN / 64; kt++) {
        __syncthreads();   // previous tile's P/V reads done
        for (int idx = tid; idx < 64 * 16; idx += 256) {
            int rr = idx >> 4, c4 = idx & 15;
            size_t gofs = kbase + (size_t)(kt * 64 + rr) * (NKV * HD) + c4 * 4;
            *(float4*)(Ks + rr * ATT_PAD + c4 * 4) = *(const float4*)(Kg + gofs);
            *(float4*)(Vs + rr * ATT_PAD + c4 * 4) = *(const float4*)(Vg + gofs);
        }
        __syncthreads();

        // S = (Q/8) K^T for this thread's 16 columns c = 4j+g
        float s[16];
        #pragma unroll
        for (int j = 0; j < 16; j++) s[j] = 0.f;
        #pragma unroll
        for (int d4 = 0; d4 < 16; d4++) {
            float4 qv = *(const float4*)(Qs + r * ATT_PAD + d4 * 4);
            #pragma unroll
            for (int j = 0; j < 16; j++) {
                float4 kv = *(const float4*)(Ks + (4 * j + g) * ATT_PAD + d4 * 4);
                s[j] += qv.x * kv.x + qv.y * kv.y + qv.z * kv.z + qv.w * kv.w;
            }
        }

        // online softmax (reduce across the 4-thread group: lane bits 0..1)
        float mt = s[0];
        #pragma unroll
        for (int j = 1; j < 16; j++) mt = fmaxf(mt, s[j]);
        mt = fmaxf(mt, __shfl_xor_sync(0xffffffffu, mt, 1));
        mt = fmaxf(mt, __shfl_xor_sync(0xffffffffu, mt, 2));
        float m_new = fmaxf(m, mt);
        float alpha = __expf(m - m_new);
        float lt = 0.f;
        #pragma unroll
        for (int j = 0; j < 16; j++) { s[j] = __expf(s[j] - m_new); lt += s[j]; }
        lt += __shfl_xor_sync(0xffffffffu, lt, 1);
        lt += __shfl_xor_sync(0xffffffffu, lt, 2);
        l = l * alpha + lt;
        m = m_new;
        #pragma unroll
        for (int u = 0; u < 16; u++) o[u] *= alpha;

        __syncthreads();   // all K reads done, safe to overwrite with P
        #pragma unroll
        for (int j = 0; j < 16; j++) Ks[r * ATT_PAD + 4 * j + g] = s[j];
        __syncthreads();

        // O += P * V  (thread covers its 16 d-columns, full c range)
        #pragma unroll 4
        for (int c = 0; c < 64; c++) {
            float p = Ks[r * ATT_PAD + c];
            #pragma unroll
            for (int u = 0; u < 4; u++) {
                float4 vv = *(const float4*)(Vs + c * ATT_PAD + (g + 4 * u) * 4);
                o[u * 4 + 0] += p * vv.x; o[u * 4 + 1] += p * vv.y;
                o[u * 4 + 2] += p * vv.z; o[u * 4 + 3] += p * vv.w;
            }
        }
    }

    float inv_l = 1.f / l;
    float* Op = O + ((size_t)b * S_LEN + qb * 64 + r) * D_MODEL + (size_t)qh * HD;
    #pragma unroll
    for (int u = 0; u < 4; u++) {
        float4 vv = make_float4(o[u * 4 + 0] * inv_l, o[u * 4 + 1] * inv_l,
                                o[u * 4 + 2] * inv_l, o[u * 4 + 3] * inv_l);
        *(float4*)(Op + (g + 4 * u) * 4) = vv;
    }
}

// ---------------- launch ----------------
extern "C" void kernel_launch(void* const* d_in, const int* in_sizes, int n_in,
                              void* d_out, int out_size)
{
    const float* h  = (const float*)d_in[0];
    const float* wq = (const float*)d_in[1];
    const float* wk = (const float*)d_in[2];
    const float* wv = (const float*)d_in[3];
    const float* wo = (const float*)d_in[4];
    float* out = (float*)d_out;

    float *q, *k, *v, *attn;
    cudaGetSymbolAddress((void**)&q,    g_q);
    cudaGetSymbolAddress((void**)&k,    g_k);
    cudaGetSymbolAddress((void**)&v,    g_v);
    cudaGetSymbolAddress((void**)&attn, g_attn);

    cudaFuncSetAttribute(attn_kernel,
                         cudaFuncAttributeMaxDynamicSharedMemorySize, ATT_SMEM);

    dim3 gq(D_MODEL / BN, MS / BM);        // (16, 32)
    dim3 gkv((NKV * HD) / BN, MS / BM);    // (4, 32)

    gemm_nt<<<gq, 256>>>(h, wq, q, MS, D_MODEL, D_MODEL);
    gemm_nt<<<gkv, 256>>>(h, wk, k, MS, NKV * HD, D_MODEL);
    gemm_nt<<<gkv, 256>>>(h, wv, v, MS, NKV * HD, D_MODEL);

    attn_kernel<<<dim3(S_LEN / 64, NQ, BATCH), 256, ATT_SMEM>>>(q, k, v, attn);

    gemm_nt<<<gq, 256>>>(attn, wo, out, MS, D_MODEL, D_MODEL);
}

// round 5
// speedup vs baseline: 3.2292x; 3.2292x over previous
#include <cuda_runtime.h>
#include <math.h>
#include <stdint.h>

#define D_MODEL 2048
#define S_LEN   2048
#define BATCH   2
#define NQ      32
#define NKV     8
#define HD      64
#define MS      (BATCH * S_LEN)   // 4096 rows

// ---------------- scratch (no allocation allowed) ----------------
__device__ float g_q[(size_t)MS * D_MODEL];      // 32 MB
__device__ float g_k[(size_t)MS * NKV * HD];     // 8 MB
__device__ float g_v[(size_t)MS * NKV * HD];     // 8 MB
__device__ float g_attn[(size_t)MS * D_MODEL];   // 32 MB

// ---------------- tf32 helpers ----------------
__device__ __forceinline__ float tfr(float x) {
    uint32_t r;
    asm("cvt.rna.tf32.f32 %0, %1;" : "=r"(r) : "f"(x));
    return __uint_as_float(r);
}
__device__ __forceinline__ uint32_t fu(float x) { return __float_as_uint(x); }

// d[4] += A(16x8) * B(8x8); A row-major frag, B col-major frag, tf32 in, f32 acc
__device__ __forceinline__ void mma8(float* d, const uint32_t* a, const uint32_t* b) {
    asm volatile(
        "mma.sync.aligned.m16n8k8.row.col.f32.tf32.tf32.f32 "
        "{%0,%1,%2,%3},{%4,%5,%6,%7},{%8,%9},{%0,%1,%2,%3};\n"
        : "+f"(d[0]), "+f"(d[1]), "+f"(d[2]), "+f"(d[3])
        : "r"(a[0]), "r"(a[1]), "r"(a[2]), "r"(a[3]), "r"(b[0]), "r"(b[1]));
}

// ---------------- GEMM: C[M,N] = A[M,K] * B[N,K]^T  (tf32 tensor core) -------
// 128x128x32 tile, 256 thr = 8 warps (4 M x 2 N), warp tile 32x64.
#define GA_STR 36    // A smem row stride (BK=32 + 4): fragment LDS conflict-free
#define GB_STR 136   // B smem row stride (BN=128 + 8): fragment LDS conflict-free

__global__ __launch_bounds__(256, 2) void gemm_tf32(const float* __restrict__ A,
                                                    const float* __restrict__ B,
                                                    float* __restrict__ C,
                                                    int M, int N, int K)
{
    __shared__ float As[128 * GA_STR];   // [m][k]
    __shared__ float Bs[32 * GB_STR];    // [k][n]   (Bs[k][n] = B[n][k])

    const int tid  = threadIdx.x;
    const int wid  = tid >> 5;
    const int lane = tid & 31;
    const int g    = lane >> 2;   // groupID
    const int c    = lane & 3;    // thread-in-group
    const int wm   = (wid & 3) * 32;
    const int wn   = (wid >> 2) * 64;
    const int row0 = blockIdx.y * 128;
    const int col0 = blockIdx.x * 128;

    // staging: each thread 16 floats of A (row am, k ak..ak+15) and of B
    const int am = tid & 127;
    const int ak = (tid >> 7) * 16;

    const float* Ag = A + (size_t)(row0 + am) * K + ak;
    const float* Bg = B + (size_t)(col0 + am) * K + ak;

    float4 ra[4], rb[4];
    #pragma unroll
    for (int i = 0; i < 4; i++) {
        ra[i] = *(const float4*)(Ag + i * 4);
        rb[i] = *(const float4*)(Bg + i * 4);
    }

    float acc[2][8][4];
    #pragma unroll
    for (int i = 0; i < 2; i++)
        #pragma unroll
        for (int j = 0; j < 8; j++)
            #pragma unroll
            for (int t = 0; t < 4; t++) acc[i][j][t] = 0.f;

    const int NIT = K / 32;
    for (int it = 0; it < NIT; it++) {
        if (it) __syncthreads();
        // stage (with cvt.rna to tf32)
        #pragma unroll
        for (int i = 0; i < 4; i++) {
            float4 a = ra[i];
            *(float4*)&As[am * GA_STR + ak + i * 4] =
                make_float4(tfr(a.x), tfr(a.y), tfr(a.z), tfr(a.w));
            float4 b = rb[i];
            Bs[(ak + i * 4 + 0) * GB_STR + am] = tfr(b.x);
            Bs[(ak + i * 4 + 1) * GB_STR + am] = tfr(b.y);
            Bs[(ak + i * 4 + 2) * GB_STR + am] = tfr(b.z);
            Bs[(ak + i * 4 + 3) * GB_STR + am] = tfr(b.w);
        }
        __syncthreads();
        // prefetch next tile while computing
        if (it + 1 < NIT) {
            Ag += 32; Bg += 32;
            #pragma unroll
            for (int i = 0; i < 4; i++) {
                ra[i] = *(const float4*)(Ag + i * 4);
                rb[i] = *(const float4*)(Bg + i * 4);
            }
        }
        // compute: 4 k-steps of 8
        #pragma unroll
        for (int ks = 0; ks < 4; ks++) {
            uint32_t af[2][4];
            #pragma unroll
            for (int i = 0; i < 2; i++) {
                const float* ab = &As[(wm + i * 16 + g) * GA_STR + ks * 8 + c];
                af[i][0] = fu(ab[0]);
                af[i][1] = fu(ab[8 * GA_STR]);
                af[i][2] = fu(ab[4]);
                af[i][3] = fu(ab[8 * GA_STR + 4]);
            }
            #pragma unroll
            for (int j = 0; j < 8; j++) {
                uint32_t bf[2];
                const float* bb = &Bs[(ks * 8 + c) * GB_STR + wn + j * 8 + g];
                bf[0] = fu(bb[0]);
                bf[1] = fu(bb[4 * GB_STR]);
                mma8(acc[0][j], af[0], bf);
                mma8(acc[1][j], af[1], bf);
            }
        }
    }

    // epilogue: C-fragment layout -> float2 stores
    #pragma unroll
    for (int i = 0; i < 2; i++) {
        #pragma unroll
        for (int j = 0; j < 8; j++) {
            int r  = row0 + wm + i * 16 + g;
            int cc = col0 + wn + j * 8 + 2 * c;
            *(float2*)&C[(size_t)r * N + cc]       = make_float2(acc[i][j][0], acc[i][j][1]);
            *(float2*)&C[(size_t)(r + 8) * N + cc] = make_float2(acc[i][j][2], acc[i][j][3]);
        }
    }
}

// ---------------- flash attention (tf32 tensor core) ----------------
// CTA: 128 q-rows of one head; KV tiles of 64. 8 warps, each owns 16 full rows
// (warp tile 16x64) so softmax reduces only within lane-quads.
#define QSTR 68
#define KSTR 68
#define VSTR 72
#define PSTR 68
#define ATT_SMEM_F (128 * QSTR + 64 * KSTR + 64 * VSTR + 128 * PSTR)
#define ATT_SMEM   (ATT_SMEM_F * 4)   // 105472 B

__global__ __launch_bounds__(256, 2) void attn_mma(const float* __restrict__ Q,
                                                   const float* __restrict__ Kg,
                                                   const float* __restrict__ Vg,
                                                   float* __restrict__ O)
{
    extern __shared__ float sm[];
    float* Qs = sm;                    // [128][QSTR]  (pre-scaled, tf32)
    float* Ks = Qs + 128 * QSTR;       // [64][KSTR]   (n=kv, k=hd)
    float* Vs = Ks + 64 * KSTR;        // [64][VSTR]   (k=kv, n=hd)
    float* Ps = Vs + 64 * VSTR;        // [128][PSTR]

    const int tid  = threadIdx.x;
    const int wid  = tid >> 5;
    const int lane = tid & 31;
    const int g    = lane >> 2;
    const int c    = lane & 3;
    const int mw   = wid * 16;         // warp's row base in tile

    const int qb  = blockIdx.x;        // 0..15
    const int qh  = blockIdx.y;        // 0..31
    const int b   = blockIdx.z;
    const int kvh = qh >> 2;

    const size_t qbase = ((size_t)b * S_LEN + qb * 128) * D_MODEL + (size_t)qh * HD;
    const size_t kbase = (size_t)b * S_LEN * (NKV * HD) + (size_t)kvh * HD;

    // load Q (scale 1/8, cvt tf32)
    for (int idx = tid; idx < 128 * 16; idx += 256) {
        int rr = idx >> 4, c4 = idx & 15;
        float4 v = *(const float4*)(Q + qbase + (size_t)rr * D_MODEL + c4 * 4);
        *(float4*)(Qs + rr * QSTR + c4 * 4) =
            make_float4(tfr(v.x * 0.125f), tfr(v.y * 0.125f),
                        tfr(v.z * 0.125f), tfr(v.w * 0.125f));
    }

    float m0 = -1e30f, m1 = -1e30f, l0 = 0.f, l1 = 0.f;
    float o[8][4];
    #pragma unroll
    for (int j = 0; j < 8; j++)
        #pragma unroll
        for (int t = 0; t < 4; t++) o[j][t] = 0.f;

    for (int kt = 0; kt < S_LEN / 64; kt++) {
        __syncthreads();   // prior tile's K/V reads complete
        for (int idx = tid; idx < 64 * 16; idx += 256) {
            int rr = idx >> 4, c4 = idx & 15;
            size_t go = kbase + (size_t)(kt * 64 + rr) * (NKV * HD) + c4 * 4;
            float4 kv = *(const float4*)(Kg + go);
            *(float4*)(Ks + rr * KSTR + c4 * 4) =
                make_float4(tfr(kv.x), tfr(kv.y), tfr(kv.z), tfr(kv.w));
            float4 vv = *(const float4*)(Vg + go);
            *(float4*)(Vs + rr * VSTR + c4 * 4) =
                make_float4(tfr(vv.x), tfr(vv.y), tfr(vv.z), tfr(vv.w));
        }
        __syncthreads();

        // ---- S = (Q/8) K^T : warp rows [mw, mw+16), all 64 kv cols ----
        float s[8][4];
        #pragma unroll
        for (int j = 0; j < 8; j++)
            #pragma unroll
            for (int t = 0; t < 4; t++) s[j][t] = 0.f;

        #pragma unroll
        for (int ks = 0; ks < 8; ks++) {
            uint32_t a[4];
            const float* ab = &Qs[(mw + g) * QSTR + ks * 8 + c];
            a[0] = fu(ab[0]);
            a[1] = fu(ab[8 * QSTR]);
            a[2] = fu(ab[4]);
            a[3] = fu(ab[8 * QSTR + 4]);
            #pragma unroll
            for (int j = 0; j < 8; j++) {
                uint32_t bf[2];
                const float* bb = &Ks[(j * 8 + g) * KSTR + ks * 8 + c];
                bf[0] = fu(bb[0]);
                bf[1] = fu(bb[4]);
                mma8(s[j], a, bf);
            }
        }

        // ---- online softmax: thread owns rows (mw+g) [s*0,s*1] and (mw+g+8) [s*2,s*3]
        float rm0 = -1e30f, rm1 = -1e30f;
        #pragma unroll
        for (int j = 0; j < 8; j++) {
            rm0 = fmaxf(rm0, fmaxf(s[j][0], s[j][1]));
            rm1 = fmaxf(rm1, fmaxf(s[j][2], s[j][3]));
        }
        rm0 = fmaxf(rm0, __shfl_xor_sync(0xffffffffu, rm0, 1));
        rm0 = fmaxf(rm0, __shfl_xor_sync(0xffffffffu, rm0, 2));
        rm1 = fmaxf(rm1, __shfl_xor_sync(0xffffffffu, rm1, 1));
        rm1 = fmaxf(rm1, __shfl_xor_sync(0xffffffffu, rm1, 2));

        float mn0 = fmaxf(m0, rm0), mn1 = fmaxf(m1, rm1);
        float al0 = __expf(m0 - mn0), al1 = __expf(m1 - mn1);
        float lt0 = 0.f, lt1 = 0.f;
        #pragma unroll
        for (int j = 0; j < 8; j++) {
            s[j][0] = __expf(s[j][0] - mn0);
            s[j][1] = __expf(s[j][1] - mn0);
            s[j][2] = __expf(s[j][2] - mn1);
            s[j][3] = __expf(s[j][3] - mn1);
            lt0 += s[j][0] + s[j][1];
            lt1 += s[j][2] + s[j][3];
        }
        lt0 += __shfl_xor_sync(0xffffffffu, lt0, 1);
        lt0 += __shfl_xor_sync(0xffffffffu, lt0, 2);
        lt1 += __shfl_xor_sync(0xffffffffu, lt1, 1);
        lt1 += __shfl_xor_sync(0xffffffffu, lt1, 2);
        l0 = l0 * al0 + lt0;  m0 = mn0;
        l1 = l1 * al1 + lt1;  m1 = mn1;
        #pragma unroll
        for (int j = 0; j < 8; j++) {
            o[j][0] *= al0; o[j][1] *= al0;
            o[j][2] *= al1; o[j][3] *= al1;
        }

        // ---- P -> smem (C-layout to A-layout), warp-private region ----
        {
            float* p0 = &Ps[(mw + g) * PSTR];
            float* p1 = &Ps[(mw + g + 8) * PSTR];
            #pragma unroll
            for (int j = 0; j < 8; j++) {
                int cc = j * 8 + 2 * c;
                p0[cc]     = tfr(s[j][0]);
                p0[cc + 1] = tfr(s[j][1]);
                p1[cc]     = tfr(s[j][2]);
                p1[cc + 1] = tfr(s[j][3]);
            }
        }
        __syncwarp();

        // ---- O += P * V ----
        #pragma unroll
        for (int ks = 0; ks < 8; ks++) {
            uint32_t a[4];
            const float* ab = &Ps[(mw + g) * PSTR + ks * 8 + c];
            a[0] = fu(ab[0]);
            a[1] = fu(ab[8 * PSTR]);
            a[2] = fu(ab[4]);
            a[3] = fu(ab[8 * PSTR + 4]);
            #pragma unroll
            for (int j = 0; j < 8; j++) {
                uint32_t bf[2];
                const float* bb = &Vs[(ks * 8 + c) * VSTR + j * 8 + g];
                bf[0] = fu(bb[0]);
                bf[1] = fu(bb[4 * VSTR]);
                mma8(o[j], a, bf);
            }
        }
        // next iteration's __syncthreads covers P WAR across lanes
    }

    // ---- epilogue: normalize and store ----
    float il0 = 1.f / l0, il1 = 1.f / l1;
    size_t r0 = ((size_t)b * S_LEN + qb * 128 + mw + g) * D_MODEL + (size_t)qh * HD;
    size_t r1 = r0 + (size_t)8 * D_MODEL;
    #pragma unroll
    for (int j = 0; j < 8; j++) {
        int cc = j * 8 + 2 * c;
        *(float2*)&O[r0 + cc] = make_float2(o[j][0] * il0, o[j][1] * il0);
        *(float2*)&O[r1 + cc] = make_float2(o[j][2] * il1, o[j][3] * il1);
    }
}

// ---------------- launch ----------------
extern "C" void kernel_launch(void* const* d_in, const int* in_sizes, int n_in,
                              void* d_out, int out_size)
{
    const float* h  = (const float*)d_in[0];
    const float* wq = (const float*)d_in[1];
    const float* wk = (const float*)d_in[2];
    const float* wv = (const float*)d_in[3];
    const float* wo = (const float*)d_in[4];
    float* out = (float*)d_out;

    float *q, *k, *v, *attn;
    cudaGetSymbolAddress((void**)&q,    g_q);
    cudaGetSymbolAddress((void**)&k,    g_k);
    cudaGetSymbolAddress((void**)&v,    g_v);
    cudaGetSymbolAddress((void**)&attn, g_attn);

    cudaFuncSetAttribute(attn_mma,
                         cudaFuncAttributeMaxDynamicSharedMemorySize, ATT_SMEM);

    dim3 gq(D_MODEL / 128, MS / 128);        // (16, 32)
    dim3 gkv((NKV * HD) / 128, MS / 128);    // (4, 32)

    gemm_tf32<<<gq, 256>>>(h, wq, q, MS, D_MODEL, D_MODEL);
    gemm_tf32<<<gkv, 256>>>(h, wk, k, MS, NKV * HD, D_MODEL);
    gemm_tf32<<<gkv, 256>>>(h, wv, v, MS, NKV * HD, D_MODEL);

    attn_mma<<<dim3(S_LEN / 128, NQ, BATCH), 256, ATT_SMEM>>>(q, k, v, attn);

    gemm_tf32<<<gq, 256>>>(attn, wo, out, MS, D_MODEL, D_MODEL);
}

// round 8
// speedup vs baseline: 5.0840x; 1.5744x over previous
#include <cuda_runtime.h>
#include <cuda_fp16.h>
#include <math.h>
#include <stdint.h>

#define D_MODEL 2048
#define S_LEN   2048
#define BATCH   2
#define NQ      32
#define NKV     8
#define HD      64
#define MS      (BATCH * S_LEN)   // 4096 rows

// ---------------- scratch (no allocation allowed) ----------------
__device__ float g_q[(size_t)MS * D_MODEL];      // 32 MB
__device__ float g_k[(size_t)MS * NKV * HD];     // 8 MB
__device__ float g_v[(size_t)MS * NKV * HD];     // 8 MB
__device__ float g_attn[(size_t)MS * D_MODEL];   // 32 MB

// ---------------- helpers ----------------
__device__ __forceinline__ uint32_t h2u(__half2 h) { return *(uint32_t*)&h; }
__device__ __forceinline__ uint32_t lds32(const __half* p) { return *(const uint32_t*)p; }

// m16n8k16 fp16 -> f32 acc.  A row-major frag (4 regs), B col-major frag (2 regs).
__device__ __forceinline__ void mma16(float* d, const uint32_t* a,
                                      uint32_t b0, uint32_t b1) {
    asm volatile(
        "mma.sync.aligned.m16n8k16.row.col.f32.f16.f16.f32 "
        "{%0,%1,%2,%3},{%4,%5,%6,%7},{%8,%9},{%0,%1,%2,%3};\n"
        : "+f"(d[0]), "+f"(d[1]), "+f"(d[2]), "+f"(d[3])
        : "r"(a[0]), "r"(a[1]), "r"(a[2]), "r"(a[3]), "r"(b0), "r"(b1));
}

// ---------------- GEMM: C[M,N] = A[M,K] * B[N,K]^T  (fp16 mma.sync) --------
// 128x128x32 tile, 256 thr = 8 warps (4 M x 2 N), warp tile 32x64.
// smem stride 40 halfs (80B): fragment LDS banks = (20*row + c) mod 32, all
// distinct across a warp. Double-buffered -> one __syncthreads per chunk.
#define GSTR 40

__global__ __launch_bounds__(256, 2) void gemm_fp16(const float* __restrict__ A,
                                                    const float* __restrict__ B,
                                                    float* __restrict__ C,
                                                    int M, int N, int K)
{
    __shared__ __half As[2][128 * GSTR];   // 2 x 10 KB
    __shared__ __half Bs[2][128 * GSTR];   // 2 x 10 KB

    const int tid  = threadIdx.x;
    const int wid  = tid >> 5;
    const int lane = tid & 31;
    const int g    = lane >> 2;
    const int c    = lane & 3;
    const int wm   = (wid & 3) * 32;
    const int wn   = (wid >> 2) * 64;
    const int row0 = blockIdx.y * 128;
    const int col0 = blockIdx.x * 128;

    // staging map: thread covers row tid/2, 16 floats at (tid&1)*16 (both A and B)
    const int sr = tid >> 1;
    const int sc = (tid & 1) * 16;
    const float* Ag = A + (size_t)(row0 + sr) * K + sc;
    const float* Bg = B + (size_t)(col0 + sr) * K + sc;

    float4 ra[4], rb[4];
    #pragma unroll
    for (int i = 0; i < 4; i++) {
        ra[i] = *(const float4*)(Ag + i * 4);
        rb[i] = *(const float4*)(Bg + i * 4);
    }

    float acc[2][8][4];
    #pragma unroll
    for (int i = 0; i < 2; i++)
        #pragma unroll
        for (int j = 0; j < 8; j++)
            #pragma unroll
            for (int t = 0; t < 4; t++) acc[i][j][t] = 0.f;

    const int nch = K / 32;
    for (int it = 0; it < nch; it++) {
        const int buf = it & 1;

        // stage: 16 floats -> 8 half2 -> two 16B stores
        {
            uint32_t w[8];
            #pragma unroll
            for (int i = 0; i < 4; i++) {
                w[2 * i]     = h2u(__floats2half2_rn(ra[i].x, ra[i].y));
                w[2 * i + 1] = h2u(__floats2half2_rn(ra[i].z, ra[i].w));
            }
            uint4* dst = (uint4*)&As[buf][sr * GSTR + sc];
            dst[0] = make_uint4(w[0], w[1], w[2], w[3]);
            dst[1] = make_uint4(w[4], w[5], w[6], w[7]);
            #pragma unroll
            for (int i = 0; i < 4; i++) {
                w[2 * i]     = h2u(__floats2half2_rn(rb[i].x, rb[i].y));
                w[2 * i + 1] = h2u(__floats2half2_rn(rb[i].z, rb[i].w));
            }
            dst = (uint4*)&Bs[buf][sr * GSTR + sc];
            dst[0] = make_uint4(w[0], w[1], w[2], w[3]);
            dst[1] = make_uint4(w[4], w[5], w[6], w[7]);
        }
        __syncthreads();

        // prefetch next chunk
        if (it + 1 < nch) {
            const float* ap = Ag + (it + 1) * 32;
            const float* bp = Bg + (it + 1) * 32;
            #pragma unroll
            for (int i = 0; i < 4; i++) {
                ra[i] = *(const float4*)(ap + i * 4);
                rb[i] = *(const float4*)(bp + i * 4);
            }
        }

        // compute: 2 k16 steps
        #pragma unroll
        for (int ks = 0; ks < 2; ks++) {
            uint32_t af[2][4];
            #pragma unroll
            for (int i = 0; i < 2; i++) {
                const __half* ab = &As[buf][(wm + i * 16 + g) * GSTR + ks * 16];
                af[i][0] = lds32(ab + 2 * c);
                af[i][1] = lds32(ab + 8 * GSTR + 2 * c);
                af[i][2] = lds32(ab + 8 + 2 * c);
                af[i][3] = lds32(ab + 8 * GSTR + 8 + 2 * c);
            }
            #pragma unroll
            for (int j = 0; j < 8; j++) {
                const __half* bb = &Bs[buf][(wn + j * 8 + g) * GSTR + ks * 16];
                uint32_t b0 = lds32(bb + 2 * c);
                uint32_t b1 = lds32(bb + 8 + 2 * c);
                mma16(acc[0][j], af[0], b0, b1);
                mma16(acc[1][j], af[1], b0, b1);
            }
        }
        // single sync per chunk is sufficient with double buffering:
        // next iteration's STS targets buf^1, last read before the sync above.
    }

    #pragma unroll
    for (int i = 0; i < 2; i++) {
        #pragma unroll
        for (int j = 0; j < 8; j++) {
            int r  = row0 + wm + i * 16 + g;
            int cc = col0 + wn + j * 8 + 2 * c;
            *(float2*)&C[(size_t)r * N + cc]       = make_float2(acc[i][j][0], acc[i][j][1]);
            *(float2*)&C[(size_t)(r + 8) * N + cc] = make_float2(acc[i][j][2], acc[i][j][3]);
        }
    }
}

// ---------------- flash attention (fp16 mma.sync) ----------------
// CTA: 128 q-rows of one head; KV tiles of 64. 8 warps, warp tile 16x64.
// smem stride 72 halfs (144B): fragment banks = (4*row + c) mod 32, distinct.
// V stored transposed [d][kv] so PV B-fragments are contiguous half2 pairs.
#define ASTR 72
#define ATT_SMEM ((128 * ASTR + 64 * ASTR + 64 * ASTR + 128 * ASTR) * 2)  // 55296 B

__global__ __launch_bounds__(256, 2) void attn_fp16(const float* __restrict__ Q,
                                                    const float* __restrict__ Kg,
                                                    const float* __restrict__ Vg,
                                                    float* __restrict__ O)
{
    extern __shared__ __half sm[];
    __half* Qs = sm;                   // [128][ASTR] rows=q, cols=d (pre-scaled)
    __half* Ks = Qs + 128 * ASTR;      // [64][ASTR]  rows=kv, cols=d
    __half* Vs = Ks + 64 * ASTR;       // [64][ASTR]  rows=d, cols=kv (TRANSPOSED)
    __half* Ps = Vs + 64 * ASTR;       // [128][ASTR] rows=q, cols=kv

    const int tid  = threadIdx.x;
    const int wid  = tid >> 5;
    const int lane = tid & 31;
    const int g    = lane >> 2;
    const int c    = lane & 3;
    const int mw   = wid * 16;

    const int qb  = blockIdx.x;
    const int qh  = blockIdx.y;
    const int b   = blockIdx.z;
    const int kvh = qh >> 2;

    const size_t qbase = ((size_t)b * S_LEN + qb * 128) * D_MODEL + (size_t)qh * HD;
    const size_t kbase = (size_t)b * S_LEN * (NKV * HD) + (size_t)kvh * HD;

    // load Q (scale 1/8)
    for (int idx = tid; idx < 128 * 16; idx += 256) {
        int rr = idx >> 4, c4 = idx & 15;
        float4 v = *(const float4*)(Q + qbase + (size_t)rr * D_MODEL + c4 * 4);
        uint2 w;
        w.x = h2u(__floats2half2_rn(v.x * 0.125f, v.y * 0.125f));
        w.y = h2u(__floats2half2_rn(v.z * 0.125f, v.w * 0.125f));
        *(uint2*)&Qs[rr * ASTR + c4 * 4] = w;
    }

    // V transpose staging map
    const int vp  = tid & 31;    // kv column pair 0..31
    const int vdq = tid >> 5;    // d quad 0..7 (plus +8 pass)

    float m0 = -1e30f, m1 = -1e30f, l0 = 0.f, l1 = 0.f;
    float o[8][4];
    #pragma unroll
    for (int j = 0; j < 8; j++)
        #pragma unroll
        for (int t = 0; t < 4; t++) o[j][t] = 0.f;

    for (int kt = 0; kt < S_LEN / 64; kt++) {
        __syncthreads();   // prior tile's K/V/P reads complete
        // K: coalesced rows
        for (int idx = tid; idx < 64 * 16; idx += 256) {
            int rr = idx >> 4, c4 = idx & 15;
            float4 kv = *(const float4*)(Kg + kbase +
                         (size_t)(kt * 64 + rr) * (NKV * HD) + c4 * 4);
            uint2 w;
            w.x = h2u(__floats2half2_rn(kv.x, kv.y));
            w.y = h2u(__floats2half2_rn(kv.z, kv.w));
            *(uint2*)&Ks[rr * ASTR + c4 * 4] = w;
        }
        // V: transposed into Vs[d][kv]
        #pragma unroll
        for (int pass = 0; pass < 2; pass++) {
            int dq = vdq + pass * 8;   // d quad 0..15
            size_t r0 = kbase + (size_t)(kt * 64 + 2 * vp) * (NKV * HD) + dq * 4;
            float4 va = *(const float4*)(Vg + r0);
            float4 vb = *(const float4*)(Vg + r0 + NKV * HD);
            *(__half2*)&Vs[(4 * dq + 0) * ASTR + 2 * vp] = __floats2half2_rn(va.x, vb.x);
            *(__half2*)&Vs[(4 * dq + 1) * ASTR + 2 * vp] = __floats2half2_rn(va.y, vb.y);
            *(__half2*)&Vs[(4 * dq + 2) * ASTR + 2 * vp] = __floats2half2_rn(va.z, vb.z);
            *(__half2*)&Vs[(4 * dq + 3) * ASTR + 2 * vp] = __floats2half2_rn(va.w, vb.w);
        }
        __syncthreads();

        // ---- S = (Q/8) K^T ----
        float s[8][4];
        #pragma unroll
        for (int j = 0; j < 8; j++)
            #pragma unroll
            for (int t = 0; t < 4; t++) s[j][t] = 0.f;

        #pragma unroll
        for (int ks = 0; ks < 4; ks++) {
            uint32_t a[4];
            const __half* ab = &Qs[(mw + g) * ASTR + ks * 16];
            a[0] = lds32(ab + 2 * c);
            a[1] = lds32(ab + 8 * ASTR + 2 * c);
            a[2] = lds32(ab + 8 + 2 * c);
            a[3] = lds32(ab + 8 * ASTR + 8 + 2 * c);
            #pragma unroll
            for (int j = 0; j < 8; j++) {
                const __half* bb = &Ks[(j * 8 + g) * ASTR + ks * 16];
                mma16(s[j], a, lds32(bb + 2 * c), lds32(bb + 8 + 2 * c));
            }
        }

        // ---- online softmax (rows mw+g and mw+g+8; quad reduction) ----
        float rm0 = -1e30f, rm1 = -1e30f;
        #pragma unroll
        for (int j = 0; j < 8; j++) {
            rm0 = fmaxf(rm0, fmaxf(s[j][0], s[j][1]));
            rm1 = fmaxf(rm1, fmaxf(s[j][2], s[j][3]));
        }
        rm0 = fmaxf(rm0, __shfl_xor_sync(0xffffffffu, rm0, 1));
        rm0 = fmaxf(rm0, __shfl_xor_sync(0xffffffffu, rm0, 2));
        rm1 = fmaxf(rm1, __shfl_xor_sync(0xffffffffu, rm1, 1));
        rm1 = fmaxf(rm1, __shfl_xor_sync(0xffffffffu, rm1, 2));

        float mn0 = fmaxf(m0, rm0), mn1 = fmaxf(m1, rm1);
        float al0 = __expf(m0 - mn0), al1 = __expf(m1 - mn1);
        float lt0 = 0.f, lt1 = 0.f;
        #pragma unroll
        for (int j = 0; j < 8; j++) {
            s[j][0] = __expf(s[j][0] - mn0);
            s[j][1] = __expf(s[j][1] - mn0);
            s[j][2] = __expf(s[j][2] - mn1);
            s[j][3] = __expf(s[j][3] - mn1);
            lt0 += s[j][0] + s[j][1];
            lt1 += s[j][2] + s[j][3];
        }
        lt0 += __shfl_xor_sync(0xffffffffu, lt0, 1);
        lt0 += __shfl_xor_sync(0xffffffffu, lt0, 2);
        lt1 += __shfl_xor_sync(0xffffffffu, lt1, 1);
        lt1 += __shfl_xor_sync(0xffffffffu, lt1, 2);
        l0 = l0 * al0 + lt0;  m0 = mn0;
        l1 = l1 * al1 + lt1;  m1 = mn1;
        #pragma unroll
        for (int j = 0; j < 8; j++) {
            o[j][0] *= al0; o[j][1] *= al0;
            o[j][2] *= al1; o[j][3] *= al1;
        }

        // ---- P -> smem (warp-private rows), fp16 ----
        {
            __half* p0 = &Ps[(mw + g) * ASTR];
            __half* p1 = &Ps[(mw + g + 8) * ASTR];
            #pragma unroll
            for (int j = 0; j < 8; j++) {
                int cc = j * 8 + 2 * c;
                *(__half2*)&p0[cc] = __floats2half2_rn(s[j][0], s[j][1]);
                *(__half2*)&p1[cc] = __floats2half2_rn(s[j][2], s[j][3]);
            }
        }
        __syncwarp();

        // ---- O += P * V  (B from transposed Vs[d][kv]) ----
        #pragma unroll
        for (int ks = 0; ks < 4; ks++) {
            uint32_t a[4];
            const __half* ab = &Ps[(mw + g) * ASTR + ks * 16];
            a[0] = lds32(ab + 2 * c);
            a[1] = lds32(ab + 8 * ASTR + 2 * c);
            a[2] = lds32(ab + 8 + 2 * c);
            a[3] = lds32(ab + 8 * ASTR + 8 + 2 * c);
            #pragma unroll
            for (int j = 0; j < 8; j++) {
                const __half* bb = &Vs[(j * 8 + g) * ASTR + ks * 16];
                mma16(o[j], a, lds32(bb + 2 * c), lds32(bb + 8 + 2 * c));
            }
        }
    }

    // ---- epilogue ----
    float il0 = 1.f / l0, il1 = 1.f / l1;
    size_t r0 = ((size_t)b * S_LEN + qb * 128 + mw + g) * D_MODEL + (size_t)qh * HD;
    size_t r1 = r0 + (size_t)8 * D_MODEL;
    #pragma unroll
    for (int j = 0; j < 8; j++) {
        int cc = j * 8 + 2 * c;
        *(float2*)&O[r0 + cc] = make_float2(o[j][0] * il0, o[j][1] * il0);
        *(float2*)&O[r1 + cc] = make_float2(o[j][2] * il1, o[j][3] * il1);
    }
}

// ---------------- launch ----------------
extern "C" void kernel_launch(void* const* d_in, const int* in_sizes, int n_in,
                              void* d_out, int out_size)
{
    const float* h  = (const float*)d_in[0];
    const float* wq = (const float*)d_in[1];
    const float* wk = (const float*)d_in[2];
    const float* wv = (const float*)d_in[3];
    const float* wo = (const float*)d_in[4];
    float* out = (float*)d_out;

    float *q, *k, *v, *attn;
    cudaGetSymbolAddress((void**)&q,    g_q);
    cudaGetSymbolAddress((void**)&k,    g_k);
    cudaGetSymbolAddress((void**)&v,    g_v);
    cudaGetSymbolAddress((void**)&attn, g_attn);

    cudaFuncSetAttribute(attn_fp16,
                         cudaFuncAttributeMaxDynamicSharedMemorySize, ATT_SMEM);

    dim3 gq(D_MODEL / 128, MS / 128);        // (16, 32)
    dim3 gkv((NKV * HD) / 128, MS / 128);    // (4, 32)

    gemm_fp16<<<gq, 256>>>(h, wq, q, MS, D_MODEL, D_MODEL);
    gemm_fp16<<<gkv, 256>>>(h, wk, k, MS, NKV * HD, D_MODEL);
    gemm_fp16<<<gkv, 256>>>(h, wv, v, MS, NKV * HD, D_MODEL);

    attn_fp16<<<dim3(S_LEN / 128, NQ, BATCH), 256, ATT_SMEM>>>(q, k, v, attn);

    gemm_fp16<<<gq, 256>>>(attn, wo, out, MS, D_MODEL, D_MODEL);
}

// round 10
// speedup vs baseline: 7.1941x; 1.4150x over previous
#include <cuda_runtime.h>
#include <cuda_fp16.h>
#include <math.h>
#include <stdint.h>

#define D_MODEL 2048
#define S_LEN   2048
#define BATCH   2
#define NQ      32
#define NKV     8
#define HD      64
#define MS      (BATCH * S_LEN)   // 4096 rows

// ---------------- scratch (no allocation allowed) ----------------
__device__ __half g_qh[(size_t)MS * D_MODEL];     // 16 MB  [token][2048]
__device__ __half g_kh[(size_t)MS * NKV * HD];    // 4 MB   [token][512]
__device__ __half g_vt[(size_t)NKV * HD * MS];    // 4 MB   [512][4096] (transposed)
__device__ __half g_at[(size_t)MS * D_MODEL];     // 16 MB  [token][2048]

// ---------------- helpers ----------------
__device__ __forceinline__ uint32_t h2u(__half2 h) { return *(uint32_t*)&h; }
__device__ __forceinline__ uint32_t lds32(const __half* p) { return *(const uint32_t*)p; }
__device__ __forceinline__ uint32_t smem_u32(const void* p) {
    uint32_t a;
    asm("{ .reg .u64 t; cvta.to.shared.u64 t, %1; cvt.u32.u64 %0, t; }" : "=r"(a) : "l"(p));
    return a;
}

__device__ __forceinline__ void mma16(float* d, const uint32_t* a,
                                      uint32_t b0, uint32_t b1) {
    asm volatile(
        "mma.sync.aligned.m16n8k16.row.col.f32.f16.f16.f32 "
        "{%0,%1,%2,%3},{%4,%5,%6,%7},{%8,%9},{%0,%1,%2,%3};\n"
        : "+f"(d[0]), "+f"(d[1]), "+f"(d[2]), "+f"(d[3])
        : "r"(a[0]), "r"(a[1]), "r"(a[2]), "r"(a[3]), "r"(b0), "r"(b1));
}

#define LDSM4(r0, r1, r2, r3, addr) \
    asm volatile("ldmatrix.sync.aligned.m8n8.x4.shared.b16 {%0,%1,%2,%3}, [%4];" \
                 : "=r"(r0), "=r"(r1), "=r"(r2), "=r"(r3) : "r"(addr))

#define CPA16(dst, src) \
    asm volatile("cp.async.cg.shared.global [%0], [%1], 16;" :: "r"(dst), "l"(src))
#define CPA_COMMIT() asm volatile("cp.async.commit_group;" ::: "memory")
#define CPA_WAIT1()  asm volatile("cp.async.wait_group 1;" ::: "memory")
#define CPA_WAIT0()  asm volatile("cp.async.wait_group 0;" ::: "memory")

// ---------------- GEMM: C[M,N] = A[M,K] * B[N,K]^T  (fp16 mma.sync) --------
// 128x128x32 tile, 8 warps (4M x 2N), warp tile 32x64, ldmatrix fragments.
#define GSTR 40

template<bool A_HALF, bool C_HALF, bool C_TRANS>
__global__ __launch_bounds__(256, 2) void gemm16(const void* __restrict__ Av,
                                                 const float* __restrict__ B,
                                                 void* __restrict__ Cv,
                                                 int M, int N, int K)
{
    __shared__ __half As[2][128 * GSTR];
    __shared__ __half Bs[2][128 * GSTR];

    const int tid  = threadIdx.x;
    const int wid  = tid >> 5;
    const int lane = tid & 31;
    const int g    = lane >> 2;
    const int c    = lane & 3;
    const int wm   = (wid & 3) * 32;
    const int wn   = (wid >> 2) * 64;
    const int row0 = blockIdx.y * 128;
    const int col0 = blockIdx.x * 128;

    // staging map: thread covers row tid/2, 16 K-elements at (tid&1)*16
    const int sr = tid >> 1;
    const int sc = (tid & 1) * 16;
    const __half* Ah = (const __half*)Av + (size_t)(row0 + sr) * K + sc;
    const float*  Af = (const float*)Av  + (size_t)(row0 + sr) * K + sc;
    const float*  Bg = B + (size_t)(col0 + sr) * K + sc;

    // ldmatrix per-lane fragment base addresses (bytes)
    const uint32_t asb = smem_u32(As);
    const uint32_t bsb = smem_u32(Bs);
    const uint32_t a_fr = asb + (uint32_t)(((wm + (lane & 15)) * GSTR + (lane >> 4) * 8) * 2);
    const uint32_t b_fr = bsb + (uint32_t)(((wn + (lane & 7) + ((lane >> 4) << 3)) * GSTR
                                            + ((lane >> 3) & 1) * 8) * 2);
    const uint32_t BUFB = 128 * GSTR * 2;   // bytes per buffer

    // prefetch chunk 0
    uint4  ha[2];
    float4 fa[4], fb[4];
    if (A_HALF) { ha[0] = *(const uint4*)(Ah); ha[1] = *(const uint4*)(Ah + 8); }
    else { fa[0]=*(const float4*)(Af); fa[1]=*(const float4*)(Af+4);
           fa[2]=*(const float4*)(Af+8); fa[3]=*(const float4*)(Af+12); }
    fb[0]=*(const float4*)(Bg); fb[1]=*(const float4*)(Bg+4);
    fb[2]=*(const float4*)(Bg+8); fb[3]=*(const float4*)(Bg+12);

    float acc[2][8][4];
    #pragma unroll
    for (int i = 0; i < 2; i++)
        #pragma unroll
        for (int j = 0; j < 8; j++)
            #pragma unroll
            for (int t = 0; t < 4; t++) acc[i][j][t] = 0.f;

    const int nch = K / 32;
    for (int it = 0; it < nch; it++) {
        const int buf = it & 1;
        // stage
        {
            uint4* da = (uint4*)&As[buf][sr * GSTR + sc];
            if (A_HALF) { da[0] = ha[0]; da[1] = ha[1]; }
            else {
                uint32_t w[8];
                #pragma unroll
                for (int i = 0; i < 4; i++) {
                    w[2*i]   = h2u(__floats2half2_rn(fa[i].x, fa[i].y));
                    w[2*i+1] = h2u(__floats2half2_rn(fa[i].z, fa[i].w));
                }
                da[0] = make_uint4(w[0], w[1], w[2], w[3]);
                da[1] = make_uint4(w[4], w[5], w[6], w[7]);
            }
            uint32_t w[8];
            #pragma unroll
            for (int i = 0; i < 4; i++) {
                w[2*i]   = h2u(__floats2half2_rn(fb[i].x, fb[i].y));
                w[2*i+1] = h2u(__floats2half2_rn(fb[i].z, fb[i].w));
            }
            uint4* db = (uint4*)&Bs[buf][sr * GSTR + sc];
            db[0] = make_uint4(w[0], w[1], w[2], w[3]);
            db[1] = make_uint4(w[4], w[5], w[6], w[7]);
        }
        __syncthreads();

        if (it + 1 < nch) {
            if (A_HALF) {
                const __half* ap = Ah + (it + 1) * 32;
                ha[0] = *(const uint4*)(ap); ha[1] = *(const uint4*)(ap + 8);
            } else {
                const float* ap = Af + (it + 1) * 32;
                fa[0]=*(const float4*)(ap); fa[1]=*(const float4*)(ap+4);
                fa[2]=*(const float4*)(ap+8); fa[3]=*(const float4*)(ap+12);
            }
            const float* bp = Bg + (it + 1) * 32;
            fb[0]=*(const float4*)(bp); fb[1]=*(const float4*)(bp+4);
            fb[2]=*(const float4*)(bp+8); fb[3]=*(const float4*)(bp+12);
        }

        #pragma unroll
        for (int ks = 0; ks < 2; ks++) {
            uint32_t af[2][4];
            #pragma unroll
            for (int i = 0; i < 2; i++)
                LDSM4(af[i][0], af[i][1], af[i][2], af[i][3],
                      a_fr + buf * BUFB + (uint32_t)((i * 16 * GSTR + ks * 16) * 2));
            #pragma unroll
            for (int jp = 0; jp < 4; jp++) {
                uint32_t b0, b1, b2, b3;
                LDSM4(b0, b1, b2, b3,
                      b_fr + buf * BUFB + (uint32_t)((jp * 16 * GSTR + ks * 16) * 2));
                mma16(acc[0][2*jp],   af[0], b0, b1);
                mma16(acc[1][2*jp],   af[1], b0, b1);
                mma16(acc[0][2*jp+1], af[0], b2, b3);
                mma16(acc[1][2*jp+1], af[1], b2, b3);
            }
        }
    }

    // epilogue
    #pragma unroll
    for (int i = 0; i < 2; i++) {
        #pragma unroll
        for (int j = 0; j < 8; j++) {
            int r  = row0 + wm + i * 16 + g;
            int cc = col0 + wn + j * 8 + 2 * c;
            if (C_TRANS) {   // half, C^T layout [N][M]
                __half* Ct = (__half*)Cv;
                Ct[(size_t)cc * M + r]           = __float2half_rn(acc[i][j][0]);
                Ct[(size_t)(cc + 1) * M + r]     = __float2half_rn(acc[i][j][1]);
                Ct[(size_t)cc * M + r + 8]       = __float2half_rn(acc[i][j][2]);
                Ct[(size_t)(cc + 1) * M + r + 8] = __float2half_rn(acc[i][j][3]);
            } else if (C_HALF) {
                __half* C = (__half*)Cv;
                *(__half2*)&C[(size_t)r * N + cc] =
                    __floats2half2_rn(acc[i][j][0], acc[i][j][1]);
                *(__half2*)&C[(size_t)(r + 8) * N + cc] =
                    __floats2half2_rn(acc[i][j][2], acc[i][j][3]);
            } else {
                float* C = (float*)Cv;
                *(float2*)&C[(size_t)r * N + cc]       = make_float2(acc[i][j][0], acc[i][j][1]);
                *(float2*)&C[(size_t)(r + 8) * N + cc] = make_float2(acc[i][j][2], acc[i][j][3]);
            }
        }
    }
}

// ---------------- flash attention (fp16, regs-P, ldmatrix, cp.async) --------
// CTA: 128 q-rows of one head; KV tiles of 64, double-buffered via cp.async.
// 8 warps, warp tile 16x64. Q fragments hoisted from global. P stays in regs.
#define ASTR 72   // halfs; 144B rows -> ldmatrix conflict-free

__global__ __launch_bounds__(256, 2) void attn2(const __half* __restrict__ Q,
                                                const __half* __restrict__ Kh,
                                                const __half* __restrict__ Vt,
                                                __half* __restrict__ O)
{
    __shared__ __half Ks[2][64 * ASTR];   // [kv][d]
    __shared__ __half Vs[2][64 * ASTR];   // [d][kv] (Vt source already transposed)

    const int tid  = threadIdx.x;
    const int wid  = tid >> 5;
    const int lane = tid & 31;
    const int g    = lane >> 2;
    const int c    = lane & 3;
    const int mw   = wid * 16;

    const int qb  = blockIdx.x;
    const int qh  = blockIdx.y;
    const int b   = blockIdx.z;
    const int kvh = qh >> 2;

    const uint32_t ksb = smem_u32(Ks);
    const uint32_t vsb = smem_u32(Vs);
    const uint32_t BUFB = 64 * ASTR * 2;

    // per-lane ldmatrix fragment base (same formula for K and V tiles)
    const uint32_t fr_off = (uint32_t)((((lane & 7) + ((lane >> 4) << 3)) * ASTR
                                        + ((lane >> 3) & 1) * 8) * 2);

    // staging coords: 4 chunks of 16B per thread (2 K rows-halves, 2 V)
    // chunk ch in [0,512): K, row=ch>>3, col8=(ch&7)*8 ; [512,1024): V likewise
    const size_t kgbase = (size_t)(b * S_LEN) * (NKV * HD) + (size_t)kvh * HD;
    const size_t vgbase = (size_t)(kvh * HD) * MS + (size_t)b * S_LEN;

    auto stage = [&](int kt, int buf) {
        #pragma unroll
        for (int p = 0; p < 2; p++) {
            int ch  = tid + p * 256;
            int row = ch >> 3, c8 = (ch & 7) * 8;
            const __half* src = Kh + kgbase + (size_t)(kt * 64 + row) * (NKV * HD) + c8;
            CPA16(ksb + buf * BUFB + (uint32_t)((row * ASTR + c8) * 2), src);
        }
        #pragma unroll
        for (int p = 0; p < 2; p++) {
            int ch  = tid + p * 256;
            int row = ch >> 3, c8 = (ch & 7) * 8;
            const __half* src = Vt + vgbase + (size_t)row * MS + kt * 64 + c8;
            CPA16(vsb + buf * BUFB + (uint32_t)((row * ASTR + c8) * 2), src);
        }
    };

    // hoisted Q fragments (scale folded into softmax)
    uint32_t qf[4][4];
    {
        const __half* qp = Q + ((size_t)(b * S_LEN + qb * 128 + mw + g)) * D_MODEL
                             + (size_t)qh * HD;
        const __half* qp8 = qp + (size_t)8 * D_MODEL;
        #pragma unroll
        for (int ks = 0; ks < 4; ks++) {
            qf[ks][0] = lds32(qp  + ks * 16 + 2 * c);
            qf[ks][1] = lds32(qp8 + ks * 16 + 2 * c);
            qf[ks][2] = lds32(qp  + ks * 16 + 8 + 2 * c);
            qf[ks][3] = lds32(qp8 + ks * 16 + 8 + 2 * c);
        }
    }

    float m0 = -1e30f, m1 = -1e30f, l0 = 0.f, l1 = 0.f;
    float o[8][4];
    #pragma unroll
    for (int j = 0; j < 8; j++)
        #pragma unroll
        for (int t = 0; t < 4; t++) o[j][t] = 0.f;

    stage(0, 0);
    CPA_COMMIT();

    const int NTILE = S_LEN / 64;
    for (int kt = 0; kt < NTILE; kt++) {
        const int buf = kt & 1;
        if (kt + 1 < NTILE) { stage(kt + 1, buf ^ 1); CPA_COMMIT(); CPA_WAIT1(); }
        else                { CPA_WAIT0(); }
        __syncthreads();

        // ---- S = Q K^T ----
        float s[8][4];
        #pragma unroll
        for (int j = 0; j < 8; j++)
            #pragma unroll
            for (int t = 0; t < 4; t++) s[j][t] = 0.f;

        #pragma unroll
        for (int jp = 0; jp < 4; jp++) {
            #pragma unroll
            for (int ks = 0; ks < 4; ks++) {
                uint32_t b0, b1, b2, b3;
                LDSM4(b0, b1, b2, b3,
                      ksb + buf * BUFB + fr_off + (uint32_t)((jp * 16 * ASTR + ks * 16) * 2));
                mma16(s[2*jp],   qf[ks], b0, b1);
                mma16(s[2*jp+1], qf[ks], b2, b3);
            }
        }

        // ---- scale + online softmax ----
        #pragma unroll
        for (int j = 0; j < 8; j++)
            #pragma unroll
            for (int t = 0; t < 4; t++) s[j][t] *= 0.125f;

        float rm0 = -1e30f, rm1 = -1e30f;
        #pragma unroll
        for (int j = 0; j < 8; j++) {
            rm0 = fmaxf(rm0, fmaxf(s[j][0], s[j][1]));
            rm1 = fmaxf(rm1, fmaxf(s[j][2], s[j][3]));
        }
        rm0 = fmaxf(rm0, __shfl_xor_sync(0xffffffffu, rm0, 1));
        rm0 = fmaxf(rm0, __shfl_xor_sync(0xffffffffu, rm0, 2));
        rm1 = fmaxf(rm1, __shfl_xor_sync(0xffffffffu, rm1, 1));
        rm1 = fmaxf(rm1, __shfl_xor_sync(0xffffffffu, rm1, 2));

        float mn0 = fmaxf(m0, rm0), mn1 = fmaxf(m1, rm1);
        float al0 = __expf(m0 - mn0), al1 = __expf(m1 - mn1);
        float lt0 = 0.f, lt1 = 0.f;
        #pragma unroll
        for (int j = 0; j < 8; j++) {
            s[j][0] = __expf(s[j][0] - mn0);
            s[j][1] = __expf(s[j][1] - mn0);
            s[j][2] = __expf(s[j][2] - mn1);
            s[j][3] = __expf(s[j][3] - mn1);
            lt0 += s[j][0] + s[j][1];
            lt1 += s[j][2] + s[j][3];
        }
        lt0 += __shfl_xor_sync(0xffffffffu, lt0, 1);
        lt0 += __shfl_xor_sync(0xffffffffu, lt0, 2);
        lt1 += __shfl_xor_sync(0xffffffffu, lt1, 1);
        lt1 += __shfl_xor_sync(0xffffffffu, lt1, 2);
        l0 = l0 * al0 + lt0;  m0 = mn0;
        l1 = l1 * al1 + lt1;  m1 = mn1;
        #pragma unroll
        for (int j = 0; j < 8; j++) {
            o[j][0] *= al0; o[j][1] *= al0;
            o[j][2] *= al1; o[j][3] *= al1;
        }

        // ---- P fragments in registers (C-frag == A-frag layout) ----
        uint32_t pf[4][4];
        #pragma unroll
        for (int ks = 0; ks < 4; ks++) {
            pf[ks][0] = h2u(__floats2half2_rn(s[2*ks][0],   s[2*ks][1]));
            pf[ks][1] = h2u(__floats2half2_rn(s[2*ks][2],   s[2*ks][3]));
            pf[ks][2] = h2u(__floats2half2_rn(s[2*ks+1][0], s[2*ks+1][1]));
            pf[ks][3] = h2u(__floats2half2_rn(s[2*ks+1][2], s[2*ks+1][3]));
        }

        // ---- O += P * V ----
        #pragma unroll
        for (int jp = 0; jp < 4; jp++) {
            #pragma unroll
            for (int ks = 0; ks < 4; ks++) {
                uint32_t b0, b1, b2, b3;
                LDSM4(b0, b1, b2, b3,
                      vsb + buf * BUFB + fr_off + (uint32_t)((jp * 16 * ASTR + ks * 16) * 2));
                mma16(o[2*jp],   pf[ks], b0, b1);
                mma16(o[2*jp+1], pf[ks], b2, b3);
            }
        }
        __syncthreads();   // all reads of buf done before it is restaged
    }

    // ---- epilogue (half output) ----
    float il0 = 1.f / l0, il1 = 1.f / l1;
    __half* Op  = O + ((size_t)(b * S_LEN + qb * 128 + mw + g)) * D_MODEL + (size_t)qh * HD;
    __half* Op8 = Op + (size_t)8 * D_MODEL;
    #pragma unroll
    for (int j = 0; j < 8; j++) {
        int cc = j * 8 + 2 * c;
        *(__half2*)&Op[cc]  = __floats2half2_rn(o[j][0] * il0, o[j][1] * il0);
        *(__half2*)&Op8[cc] = __floats2half2_rn(o[j][2] * il1, o[j][3] * il1);
    }
}

// ---------------- launch ----------------
extern "C" void kernel_launch(void* const* d_in, const int* in_sizes, int n_in,
                              void* d_out, int out_size)
{
    const float* h  = (const float*)d_in[0];
    const float* wq = (const float*)d_in[1];
    const float* wk = (const float*)d_in[2];
    const float* wv = (const float*)d_in[3];
    const float* wo = (const float*)d_in[4];
    float* out = (float*)d_out;

    __half *qh, *kh, *vt, *at;
    cudaGetSymbolAddress((void**)&qh, g_qh);
    cudaGetSymbolAddress((void**)&kh, g_kh);
    cudaGetSymbolAddress((void**)&vt, g_vt);
    cudaGetSymbolAddress((void**)&at, g_at);

    dim3 gq(D_MODEL / 128, MS / 128);        // (16, 32)
    dim3 gkv((NKV * HD) / 128, MS / 128);    // (4, 32)

    gemm16<false, true, false><<<gq, 256>>>(h, wq, qh, MS, D_MODEL, D_MODEL);
    gemm16<false, true, false><<<gkv, 256>>>(h, wk, kh, MS, NKV * HD, D_MODEL);
    gemm16<false, true, true ><<<gkv, 256>>>(h, wv, vt, MS, NKV * HD, D_MODEL);

    attn2<<<dim3(S_LEN / 128, NQ, BATCH), 256>>>(qh, kh, vt, at);

    gemm16<true, false, false><<<gq, 256>>>(at, wo, out, MS, D_MODEL, D_MODEL);
}